// round 15
// baseline (speedup 1.0000x reference)
#include <cuda_runtime.h>

#define C 100
#define DCUT 8   // pdf(d>=8) < 5e-15: exp(code)=1 there

// ===========================================================================
// Compile-time scalars only (no big table):
//   ex[d]    = exp(code(d)), code(d) = invnorm*exp(-d^2/2), d<8
//   invZ[mu] = 1 / sum_j exp(code(|j-mu|))
//   tlogt[mu]= sum_j T*log(T)
// T[mu][j] is reconstructed on the fly: EX[min(|j-mu|,8)] * invZ[mu].
// ===========================================================================
struct Small {
    float ex[DCUT];
    float invZ[C];
    float tlogt[C];
};

constexpr double cexp_t(double x) {   // 0 <= x <= 0.5, underflow-safe
    if (x < 1e-8) return 1.0 + x + 0.5 * x * x;
    double term = 1.0, sum = 1.0;
    for (int i = 1; i <= 20; ++i) {
        term *= x / (double)i;
        sum += term;
        if (term < 1e-20 * sum) break;
    }
    return sum;
}
constexpr double cpowi(double b, int e) {
    double r = 1.0;
    while (e) { if (e & 1) r *= b; e >>= 1; if (e) b *= b; }
    return r;
}
constexpr double cln1p(double u) {    // |u| <= 0.05
    double y = u / (2.0 + u);
    double y2 = y * y, term = y, sum = y;
    for (int i = 1; i <= 10; ++i) { term *= y2; sum += term / (double)(2 * i + 1); }
    return 2.0 * sum;
}

constexpr Small make_small() {
    Small s{};
    const double LN100    = 4.60517018598809136803598290936873;
    const double INV_NORM = 0.39894228040143267793994605993438;  // 1/sqrt(2pi)

    double CODE[C] = {}, EX[C] = {};
    const double p = cexp_t(0.5);              // e^{1/2}
    for (int d = 0; d < C; ++d) {
        if (d < DCUT) {
            CODE[d] = INV_NORM / cpowi(p, d * d);
            EX[d]   = cexp_t(CODE[d]);
            s.ex[d] = (float)EX[d];
        } else { CODE[d] = 0.0; EX[d] = 1.0; }
    }
    for (int mu = 0; mu < C; ++mu) {
        double Z = 0.0;
        for (int j = 0; j < C; ++j) {
            int d = j - mu; if (d < 0) d = -d;
            Z += EX[d];
        }
        s.invZ[mu] = (float)(1.0 / Z);
        const double lnZ = LN100 + cln1p((Z - 100.0) * 0.01);   // Z in [100,101.5]
        double tl = 0.0;
        for (int j = 0; j < C; ++j) {
            int d = j - mu; if (d < 0) d = -d;
            tl += (EX[d] / Z) * (CODE[d] - lnZ);
        }
        s.tlogt[mu] = (float)tl;
    }
    return s;
}

__device__ constexpr Small g_sm = make_small();

__device__ double       g_accum;   // zero-init; winner resets each run
__device__ unsigned int g_count;   // ditto

// dot-partial for 4 consecutive classes handled by one lane:
// sum_k EX[min(|j0+k - mu|,8)] * s_k    (invZ applied once per row by caller)
__device__ __forceinline__ float dot4(const float* __restrict__ exs,
                                      int j0, int mu, float4 s) {
    int d0 = min(abs(j0     - mu), 8);
    int d1 = min(abs(j0 + 1 - mu), 8);
    int d2 = min(abs(j0 + 2 - mu), 8);
    int d3 = min(abs(j0 + 3 - mu), 8);
    float p = exs[d0] * s.x;
    p = fmaf(exs[d1], s.y, p);
    p = fmaf(exs[d2], s.z, p);
    p = fmaf(exs[d3], s.w, p);
    return p;
}

// ===========================================================================
// Single fused kernel, table-free. 64 warps/SM (8 blocks x 256 thr, <1KB smem),
// exactly one full-residency wave. Grid-stride warp-per-row, 2-way unrolled.
// Only global traffic = scores + labels. Per row: warp-reduce sum(exp);
// dot vs target deferred per-lane (linear). One double atomic per block;
// last block finalizes + resets.
// ===========================================================================
__global__ void __launch_bounds__(256, 8)
LossLD_kernel(const float* __restrict__ scores,
              const int* __restrict__ labels,
              float* __restrict__ out,
              int rows) {
    __shared__ float ex_s[12];              // ex[0..7], [8..11]=1.0 pad
    __shared__ float invZ_s[C], tlogt_s[C];
    __shared__ float wsum[8];

    const int tid = threadIdx.x;
    if (tid < 12)  ex_s[tid] = (tid < DCUT) ? g_sm.ex[tid] : 1.0f;
    if (tid < C) { invZ_s[tid] = g_sm.invZ[tid]; tlogt_s[tid] = g_sm.tlogt[tid]; }
    __syncthreads();

    const int lane = tid & 31;
    const int wib  = tid >> 5;
    const int gw   = (int)((blockIdx.x * blockDim.x + tid) >> 5);
    const int W    = (int)((gridDim.x * blockDim.x) >> 5);

    const bool act = (lane < 25);
    const int  j0  = lane * 4;              // first class index for this lane
    const float4* __restrict__ sp = (const float4*)scores;

    float dotacc = 0.f;   // per-lane, reduced once at the end
    float scal   = 0.f;   // lane0: sum of (tlogt[mu] + log(sum exp))

    int r = gw;
    for (; r + W < rows; r += 2 * W) {
        const int ra = r, rb = r + W;
        int mua = __ldg(labels + ra);
        int mub = __ldg(labels + rb);
        mua = min(max(mua, 0), C - 1);
        mub = min(max(mub, 0), C - 1);

        float sea = 0.f, seb = 0.f;
        if (act) {
            float4 sa = __ldg(sp + (size_t)ra * 25 + lane);
            float4 sb = __ldg(sp + (size_t)rb * 25 + lane);
            sea = (__expf(sa.x) + __expf(sa.y)) + (__expf(sa.z) + __expf(sa.w));
            seb = (__expf(sb.x) + __expf(sb.y)) + (__expf(sb.z) + __expf(sb.w));
            dotacc = fmaf(invZ_s[mua], dot4(ex_s, j0, mua, sa), dotacc);
            dotacc = fmaf(invZ_s[mub], dot4(ex_s, j0, mub, sb), dotacc);
        }
        #pragma unroll
        for (int o = 16; o; o >>= 1) {
            sea += __shfl_xor_sync(0xffffffffu, sea, o);
            seb += __shfl_xor_sync(0xffffffffu, seb, o);
        }
        if (lane == 0)   // log a + log b = log(a*b): sums ~165 each, safe
            scal += tlogt_s[mua] + tlogt_s[mub] + __logf(sea * seb);
    }
    while (r < rows) {   // remainder rows
        int mu = __ldg(labels + r);
        mu = min(max(mu, 0), C - 1);
        float se = 0.f;
        if (act) {
            float4 s = __ldg(sp + (size_t)r * 25 + lane);
            se = (__expf(s.x) + __expf(s.y)) + (__expf(s.z) + __expf(s.w));
            dotacc = fmaf(invZ_s[mu], dot4(ex_s, j0, mu, s), dotacc);
        }
        #pragma unroll
        for (int o = 16; o; o >>= 1) se += __shfl_xor_sync(0xffffffffu, se, o);
        if (lane == 0) scal += tlogt_s[mu] + __logf(se);
        r += W;
    }

    // one-time dot reduction per warp
    #pragma unroll
    for (int o = 16; o; o >>= 1) dotacc += __shfl_xor_sync(0xffffffffu, dotacc, o);

    if (lane == 0) wsum[wib] = scal - dotacc;
    __syncthreads();
    if (tid == 0) {
        float bs = wsum[0] + wsum[1] + wsum[2] + wsum[3]
                 + wsum[4] + wsum[5] + wsum[6] + wsum[7];
        atomicAdd(&g_accum, (double)bs);
        __threadfence();
        unsigned int ticket = atomicAdd(&g_count, 1u);
        if (ticket == gridDim.x - 1) {           // last block: finalize + reset
            double total = *(volatile double*)&g_accum;
            out[0] = (float)(total / (double)rows);
            *(volatile double*)&g_accum = 0.0;   // deterministic across replays
            *(volatile unsigned int*)&g_count = 0u;
        }
    }
}

// ---------------------------------------------------------------------------
// inputs: [0] scores float32 (n*c), [1] labels int32 (n) ; output: scalar f32
// ---------------------------------------------------------------------------
extern "C" void kernel_launch(void* const* d_in, const int* in_sizes, int n_in,
                              void* d_out, int out_size) {
    const float* scores = (const float*)d_in[0];
    const int*   labels = (const int*)d_in[1];
    float*       out    = (float*)d_out;

    const int rows = in_sizes[1];   // 262144
    int blocks = 148 * 8;           // one full-residency wave: 64 warps/SM
    if (blocks * 8 > rows) blocks = (rows + 7) / 8;

    LossLD_kernel<<<blocks, 256>>>(scores, labels, out, rows);
}